// round 2
// baseline (speedup 1.0000x reference)
#include <cuda_runtime.h>
#include <math.h>

#define BB 64
#define DD 512
#define HH 8
#define EPSF 1e-8f
#define TILE_I 64
#define NTHR 256
#define ROWS_PER_WARP 8   // TILE_I / 8 warps
#define JCHUNK 16         // DD / 32 lanes

__global__ __launch_bounds__(NTHR)
void flattn_kernel(const float* __restrict__ x,
                   const float* __restrict__ alphas,
                   const float* __restrict__ betas,
                   float* __restrict__ out)
{
    __shared__ float xs[DD];
    __shared__ float sa[HH * 3];
    __shared__ float sb[HH * 3];

    const int b    = blockIdx.y;
    const int tile = blockIdx.x;          // 0..7, block of 64 i-rows
    const int tid  = threadIdx.x;
    const int warp = tid >> 5;
    const int lane = tid & 31;

    // Stage x row + per-head affine params in shared.
    const float* xrow = x + b * DD;
    #pragma unroll
    for (int k = tid; k < DD; k += NTHR) xs[k] = xrow[k];
    if (tid < HH * 3) { sa[tid] = alphas[tid]; sb[tid] = betas[tid]; }
    __syncthreads();

    // Each lane caches its 16 j-values once; reused across all heads/rows.
    float xr[JCHUNK];
    #pragma unroll
    for (int u = 0; u < JCHUNK; u++) xr[u] = xs[lane + 32 * u];

    float acc[ROWS_PER_WARP];
    #pragma unroll
    for (int r = 0; r < ROWS_PER_WARP; r++) acc[r] = 0.0f;

    const float inv_sqrt_d = 0.044194173824159216f;  // 1/sqrt(512)

    for (int h = 0; h < HH; h++) {
        const float aq = sa[h * 3 + 0];
        const float ak = sa[h * 3 + 1];
        const float av = sa[h * 3 + 2];
        const float bq = sb[h * 3 + 0];
        const float bk = sb[h * 3 + 1];
        const float bv = sb[h * 3 + 2];

        #pragma unroll
        for (int r = 0; r < ROWS_PER_WARP; r++) {
            const int i_loc = warp * ROWS_PER_WARP + r;
            const float xi = xs[tile * TILE_I + i_loc];
            const float ki = fmaf(ak, xi, bk);
            const float c  = bq - ki;      // q_j - k_i = aq*x_j + c

            // Pass 1: s_j = 1/(|q_j - k_i| + eps), track max. s kept in regs.
            float s[JCHUNK];
            float m = -3.0e38f;
            #pragma unroll
            for (int u = 0; u < JCHUNK; u++) {
                float dqk = fmaf(aq, xr[u], c);
                float t   = fabsf(dqk) + EPSF;
                float r0;
                asm("rcp.approx.f32 %0, %1;" : "=f"(r0) : "f"(t));
                // one Newton step -> ~correctly rounded reciprocal
                float err = __fmaf_rn(-t, r0, 1.0f);
                float sv  = __fmaf_rn(r0, err, r0);
                s[u] = sv;
                m = fmaxf(m, sv);
            }
            #pragma unroll
            for (int off = 16; off > 0; off >>= 1)
                m = fmaxf(m, __shfl_xor_sync(0xffffffffu, m, off));

            // Pass 2: e = exp(s - m); accumulate sum(e) and sum(e * x_j).
            float wsum = 0.0f, wx = 0.0f;
            #pragma unroll
            for (int u = 0; u < JCHUNK; u++) {
                float e = __expf(s[u] - m);
                wsum += e;
                wx = fmaf(e, xr[u], wx);
            }
            #pragma unroll
            for (int off = 16; off > 0; off >>= 1) {
                wsum += __shfl_xor_sync(0xffffffffu, wsum, off);
                wx   += __shfl_xor_sync(0xffffffffu, wx, off);
            }

            // attended_i = (av*wx + bv*wsum) / (wsum * sqrt(d))
            float num = fmaf(av, wx, bv * wsum);
            acc[r] += (num / wsum) * inv_sqrt_d;
        }
    }

    // Single non-atomic store per output element.
    #pragma unroll
    for (int r = 0; r < ROWS_PER_WARP; r++) {
        if (lane == r) {
            int i = tile * TILE_I + warp * ROWS_PER_WARP + r;
            out[b * DD + i] = xs[i] + acc[r];
        }
    }
}

extern "C" void kernel_launch(void* const* d_in, const int* in_sizes, int n_in,
                              void* d_out, int out_size)
{
    const float* x      = (const float*)d_in[0];
    const float* alphas = (const float*)d_in[1];
    const float* betas  = (const float*)d_in[2];
    float* out = (float*)d_out;

    dim3 grid(DD / TILE_I, BB);   // (8, 64) = 512 CTAs
    dim3 block(NTHR);
    flattn_kernel<<<grid, block>>>(x, alphas, betas, out);
}

// round 3
// speedup vs baseline: 1.0015x; 1.0015x over previous
#include <cuda_runtime.h>
#include <math.h>

#define BB 64
#define DD 512
#define HH 8
#define EPSF 1e-8f
#define TILE_I 32
#define NTHR 128
#define NWARPS (NTHR / 32)
#define ROWS_PER_WARP (TILE_I / NWARPS)   // 8
#define JCHUNK (DD / 32)                  // 16

__global__ __launch_bounds__(NTHR)
void flattn_kernel(const float* __restrict__ x,
                   const float* __restrict__ alphas,
                   const float* __restrict__ betas,
                   float* __restrict__ out)
{
    __shared__ float xs[DD];
    __shared__ float sa[HH * 3];
    __shared__ float sb[HH * 3];

    const int b    = blockIdx.y;
    const int tile = blockIdx.x;          // 0..15, block of 32 i-rows
    const int tid  = threadIdx.x;
    const int warp = tid >> 5;
    const int lane = tid & 31;

    const float* xrow = x + b * DD;
    #pragma unroll
    for (int k = tid; k < DD; k += NTHR) xs[k] = xrow[k];
    if (tid < HH * 3) { sa[tid] = alphas[tid]; sb[tid] = betas[tid]; }
    __syncthreads();

    // Per-lane j-slice cached in registers (reused across all heads & rows).
    float xr[JCHUNK];
    #pragma unroll
    for (int u = 0; u < JCHUNK; u++) xr[u] = xs[lane + 32 * u];

    // Per-warp i-rows cached (independent of h).
    float xi[ROWS_PER_WARP];
    #pragma unroll
    for (int r = 0; r < ROWS_PER_WARP; r++)
        xi[r] = xs[tile * TILE_I + warp * ROWS_PER_WARP + r];

    float acc[ROWS_PER_WARP];
    #pragma unroll
    for (int r = 0; r < ROWS_PER_WARP; r++) acc[r] = 0.0f;

    const float inv_sqrt_d = 0.044194173824159216f;  // 1/sqrt(512)
    const float L2E        = 1.4426950408889634f;    // log2(e)

    // Constant term: sum_h bv_h / sqrt(d), added once per output element.
    float bconst = 0.0f;
    #pragma unroll
    for (int h = 0; h < HH; h++) bconst += sb[h * 3 + 2];
    bconst *= inv_sqrt_d;

    #pragma unroll
    for (int h = 0; h < HH; h++) {
        const float aq = sa[h * 3 + 0];
        const float ak = sa[h * 3 + 1];
        const float bq = sb[h * 3 + 0];
        const float bk = sb[h * 3 + 1];
        const float avs = sa[h * 3 + 2] * inv_sqrt_d;  // av / sqrt(d)

        #pragma unroll
        for (int r = 0; r < ROWS_PER_WARP; r++) {
            const float c = bq - fmaf(ak, xi[r], bk);  // q_j - k_i = aq*x_j + c

            // Pass 1: s_j = rcp(|aq*x_j + c| + eps); track max (2-way ILP).
            float s[JCHUNK];
            float m0 = -3.0e38f, m1 = -3.0e38f;
            #pragma unroll
            for (int u = 0; u < JCHUNK; u += 2) {
                float t0 = fabsf(fmaf(aq, xr[u],     c)) + EPSF;
                float t1 = fabsf(fmaf(aq, xr[u + 1], c)) + EPSF;
                float s0, s1;
                asm("rcp.approx.f32 %0, %1;" : "=f"(s0) : "f"(t0));
                asm("rcp.approx.f32 %0, %1;" : "=f"(s1) : "f"(t1));
                s[u] = s0; s[u + 1] = s1;
                m0 = fmaxf(m0, s0);
                m1 = fmaxf(m1, s1);
            }
            float m = fmaxf(m0, m1);
            #pragma unroll
            for (int off = 16; off > 0; off >>= 1)
                m = fmaxf(m, __shfl_xor_sync(0xffffffffu, m, off));

            const float negmL2E = -m * L2E;

            // Pass 2: e = 2^(s*L2E - m*L2E); accumulate sum(e), sum(e*x_j).
            float w0 = 0.0f, w1 = 0.0f, wx0 = 0.0f, wx1 = 0.0f;
            #pragma unroll
            for (int u = 0; u < JCHUNK; u += 2) {
                float a0 = fmaf(s[u],     L2E, negmL2E);
                float a1 = fmaf(s[u + 1], L2E, negmL2E);
                float e0, e1;
                asm("ex2.approx.f32 %0, %1;" : "=f"(e0) : "f"(a0));
                asm("ex2.approx.f32 %0, %1;" : "=f"(e1) : "f"(a1));
                w0 += e0;           w1 += e1;
                wx0 = fmaf(e0, xr[u], wx0);
                wx1 = fmaf(e1, xr[u + 1], wx1);
            }
            float wsum = w0 + w1;
            float wx   = wx0 + wx1;
            #pragma unroll
            for (int off = 16; off > 0; off >>= 1) {
                wsum += __shfl_xor_sync(0xffffffffu, wsum, off);
                wx   += __shfl_xor_sync(0xffffffffu, wx, off);
            }

            float rw;
            asm("rcp.approx.f32 %0, %1;" : "=f"(rw) : "f"(wsum));
            acc[r] = fmaf(avs, wx * rw, acc[r]);
        }
    }

    // Single non-atomic store per output element.
    #pragma unroll
    for (int r = 0; r < ROWS_PER_WARP; r++) {
        if (lane == r) {
            int i = tile * TILE_I + warp * ROWS_PER_WARP + r;
            out[b * DD + i] = xs[i] + acc[r] + bconst;
        }
    }
}

extern "C" void kernel_launch(void* const* d_in, const int* in_sizes, int n_in,
                              void* d_out, int out_size)
{
    const float* x      = (const float*)d_in[0];
    const float* alphas = (const float*)d_in[1];
    const float* betas  = (const float*)d_in[2];
    float* out = (float*)d_out;

    dim3 grid(DD / TILE_I, BB);   // (16, 64) = 1024 CTAs
    dim3 block(NTHR);
    flattn_kernel<<<grid, block>>>(x, alphas, betas, out);
}

// round 6
// speedup vs baseline: 1.4430x; 1.4408x over previous
#include <cuda_runtime.h>
#include <math.h>

#define BB 64
#define DD 512
#define HH 8
#define EPSF 1e-8f
#define NTHR 128          // 8 heads x 16 i-values per CTA
#define ITILE 16
#define NTILES (DD / ITILE)   // 32

__global__ __launch_bounds__(NTHR)
void flattn_kernel(const float* __restrict__ x,
                   const float* __restrict__ alphas,
                   const float* __restrict__ betas,
                   float* __restrict__ out)
{
    __shared__ __align__(16) float xs[DD];
    __shared__ float partial[NTHR];   // [h][i_loc]

    const int b    = blockIdx.y;
    const int tile = blockIdx.x;      // 0..31, block of 16 i-rows
    const int tid  = threadIdx.x;
    const int h     = tid >> 4;       // 0..7
    const int i_loc = tid & 15;       // 0..15
    const int i     = tile * ITILE + i_loc;

    // Stage x row in shared (vectorized).
    const float4* xrow4 = (const float4*)(x + b * DD);
    float4* xs4w = (float4*)xs;
    #pragma unroll
    for (int k = tid; k < DD / 4; k += NTHR) xs4w[k] = xrow4[k];
    __syncthreads();

    // Per-thread head params (tiny, L2-resident).
    const float aq = alphas[h * 3 + 0];
    const float ak = alphas[h * 3 + 1];
    const float av = alphas[h * 3 + 2];
    const float bq = betas[h * 3 + 0];
    const float bk = betas[h * 3 + 1];

    const float inv_sqrt_d = 0.044194173824159216f;  // 1/sqrt(512)
    const float L2E        = 1.4426950408889634f;    // log2(e)

    const float xi = xs[i];
    const float c  = bq - fmaf(ak, xi, bk);   // q_j - k_i = aq*x_j + c

    const float4* xs4 = (const float4*)xs;

    // ---- Pass 1: tmin = min_j |aq*x_j + c|  (no MUFU; FMNMX w/ |.| mod) ----
    float t0 = 3.0e38f, t1 = 3.0e38f;
    #pragma unroll 4
    for (int j4 = 0; j4 < DD / 4; j4++) {
        float4 xv = xs4[j4];
        t0 = fminf(t0, fabsf(fmaf(aq, xv.x, c)));
        t1 = fminf(t1, fabsf(fmaf(aq, xv.y, c)));
        t0 = fminf(t0, fabsf(fmaf(aq, xv.z, c)));
        t1 = fminf(t1, fabsf(fmaf(aq, xv.w, c)));
    }
    float tmin = fminf(t0, t1) + EPSF;
    float m;   // m = max_j s_j = rcp(min_j t_j)  (rcp monotone decreasing)
    asm("rcp.approx.f32 %0, %1;" : "=f"(m) : "f"(tmin));
    const float negmL2E = -m * L2E;

    // ---- Pass 2: e = 2^(s*L2E - m*L2E); accumulate sum(e), sum(e*x) ----
    float w0 = 0.0f, w1 = 0.0f, wx0 = 0.0f, wx1 = 0.0f;
    #pragma unroll 4
    for (int j4 = 0; j4 < DD / 4; j4++) {
        float4 xv = xs4[j4];

        float ta = fabsf(fmaf(aq, xv.x, c)) + EPSF;
        float tb = fabsf(fmaf(aq, xv.y, c)) + EPSF;
        float tc = fabsf(fmaf(aq, xv.z, c)) + EPSF;
        float td = fabsf(fmaf(aq, xv.w, c)) + EPSF;

        float sa_, sb_, sc_, sd_;
        asm("rcp.approx.f32 %0, %1;" : "=f"(sa_) : "f"(ta));
        asm("rcp.approx.f32 %0, %1;" : "=f"(sb_) : "f"(tb));
        asm("rcp.approx.f32 %0, %1;" : "=f"(sc_) : "f"(tc));
        asm("rcp.approx.f32 %0, %1;" : "=f"(sd_) : "f"(td));

        float ea, eb, ec, ed;
        float aa = fmaf(sa_, L2E, negmL2E);
        float ab = fmaf(sb_, L2E, negmL2E);
        float ac = fmaf(sc_, L2E, negmL2E);
        float ad = fmaf(sd_, L2E, negmL2E);
        asm("ex2.approx.f32 %0, %1;" : "=f"(ea) : "f"(aa));
        asm("ex2.approx.f32 %0, %1;" : "=f"(eb) : "f"(ab));
        asm("ex2.approx.f32 %0, %1;" : "=f"(ec) : "f"(ac));
        asm("ex2.approx.f32 %0, %1;" : "=f"(ed) : "f"(ad));

        w0 += ea;  w1 += eb;  w0 += ec;  w1 += ed;
        wx0 = fmaf(ea, xv.x, wx0);
        wx1 = fmaf(eb, xv.y, wx1);
        wx0 = fmaf(ec, xv.z, wx0);
        wx1 = fmaf(ed, xv.w, wx1);
    }
    float wsum = w0 + w1;
    float wx   = wx0 + wx1;

    float rw;
    asm("rcp.approx.f32 %0, %1;" : "=f"(rw) : "f"(wsum));
    // contribution of head h to output i: (av * wx/wsum) / sqrt(d)
    partial[tid] = av * inv_sqrt_d * (wx * rw);
    __syncthreads();

    // ---- Cross-head sum (8 values per output), single coalesced store ----
    if (tid < ITILE) {
        float bconst = 0.0f;
        #pragma unroll
        for (int hh = 0; hh < HH; hh++) bconst += betas[hh * 3 + 2];

        float s = 0.0f;
        #pragma unroll
        for (int hh = 0; hh < HH; hh++) s += partial[hh * ITILE + tid];

        out[b * DD + tile * ITILE + tid] =
            xs[tile * ITILE + tid] + s + bconst * inv_sqrt_d;
    }
}

extern "C" void kernel_launch(void* const* d_in, const int* in_sizes, int n_in,
                              void* d_out, int out_size)
{
    const float* x      = (const float*)d_in[0];
    const float* alphas = (const float*)d_in[1];
    const float* betas  = (const float*)d_in[2];
    float* out = (float*)d_out;

    dim3 grid(NTILES, BB);   // (32, 64) = 2048 CTAs
    dim3 block(NTHR);
    flattn_kernel<<<grid, block>>>(x, alphas, betas, out);
}

// round 7
// speedup vs baseline: 1.5828x; 1.0969x over previous
#include <cuda_runtime.h>
#include <math.h>

#define BB 64
#define DD 512
#define HH 8
#define EPSF 1e-8f
#define NTHR 128          // 8 heads x 16 i-values per CTA
#define ITILE 16
#define NTILES (DD / ITILE)   // 32

typedef unsigned long long ull;

__device__ __forceinline__ ull pk2(float lo, float hi) {
    ull r; asm("mov.b64 %0, {%1, %2};" : "=l"(r) : "f"(lo), "f"(hi)); return r;
}
__device__ __forceinline__ void upk2(ull v, float& lo, float& hi) {
    asm("mov.b64 {%0, %1}, %2;" : "=f"(lo), "=f"(hi) : "l"(v));
}
__device__ __forceinline__ ull fma2(ull a, ull b, ull c) {
    ull r; asm("fma.rn.f32x2 %0, %1, %2, %3;" : "=l"(r) : "l"(a), "l"(b), "l"(c)); return r;
}
__device__ __forceinline__ ull add2(ull a, ull b) {
    ull r; asm("add.rn.f32x2 %0, %1, %2;" : "=l"(r) : "l"(a), "l"(b)); return r;
}

__global__ __launch_bounds__(NTHR)
void flattn_kernel(const float* __restrict__ x,
                   const float* __restrict__ alphas,
                   const float* __restrict__ betas,
                   float* __restrict__ out)
{
    __shared__ __align__(16) float xs[DD];
    __shared__ float partial[NTHR];   // [h][i_loc]

    const int b    = blockIdx.y;
    const int tile = blockIdx.x;      // 0..31, block of 16 i-rows
    const int tid  = threadIdx.x;
    const int h     = tid >> 4;       // 0..7
    const int i_loc = tid & 15;       // 0..15
    const int i     = tile * ITILE + i_loc;

    // Stage x row in shared (vectorized).
    const float4* xrow4 = (const float4*)(x + b * DD);
    float4* xs4w = (float4*)xs;
    #pragma unroll
    for (int k = tid; k < DD / 4; k += NTHR) xs4w[k] = xrow4[k];
    __syncthreads();

    // Per-thread head params (tiny, L2-resident).
    const float aq = alphas[h * 3 + 0];
    const float ak = alphas[h * 3 + 1];
    const float av = alphas[h * 3 + 2];
    const float bq = betas[h * 3 + 0];
    const float bk = betas[h * 3 + 1];

    const float inv_sqrt_d = 0.044194173824159216f;  // 1/sqrt(512)
    const float L2E        = 1.4426950408889634f;    // log2(e)

    const float xi = xs[i];
    const float c  = bq - fmaf(ak, xi, bk);   // q_j - k_i = aq*x_j + c

    const ull aq2  = pk2(aq, aq);
    const ull c2   = pk2(c, c);
    const ull L2E2 = pk2(L2E, L2E);

    const float4* xs4 = (const float4*)xs;

    // ---- Pass 1: tmin = min_j |aq*x_j + c|  (packed FFMA2 + scalar FMNMX) ----
    float t0 = 3.0e38f, t1 = 3.0e38f, t2 = 3.0e38f, t3 = 3.0e38f;
    #pragma unroll 8
    for (int j4 = 0; j4 < DD / 4; j4++) {
        float4 xv = xs4[j4];
        ull x01 = pk2(xv.x, xv.y);
        ull x23 = pk2(xv.z, xv.w);
        ull d01 = fma2(aq2, x01, c2);
        ull d23 = fma2(aq2, x23, c2);
        float da, db, dc, dd;
        upk2(d01, da, db);
        upk2(d23, dc, dd);
        t0 = fminf(t0, fabsf(da));
        t1 = fminf(t1, fabsf(db));
        t2 = fminf(t2, fabsf(dc));
        t3 = fminf(t3, fabsf(dd));
    }
    float tmin = fminf(fminf(t0, t1), fminf(t2, t3)) + EPSF;
    float m;   // m = max_j s_j = rcp(min_j t_j)  (rcp monotone decreasing)
    asm("rcp.approx.f32 %0, %1;" : "=f"(m) : "f"(tmin));
    const float negmL2E = -m * L2E;
    const ull   negm2   = pk2(negmL2E, negmL2E);

    // ---- Pass 2: e = 2^(s*L2E - m*L2E); accumulate sum(e), sum(e*x) ----
    ull w2  = 0ULL;   // packed (w0, w1)
    ull wx2 = 0ULL;   // packed (wx0, wx1)
    ull w2b  = 0ULL;
    ull wx2b = 0ULL;
    #pragma unroll 8
    for (int j4 = 0; j4 < DD / 4; j4++) {
        float4 xv = xs4[j4];
        ull x01 = pk2(xv.x, xv.y);
        ull x23 = pk2(xv.z, xv.w);

        ull d01 = fma2(aq2, x01, c2);
        ull d23 = fma2(aq2, x23, c2);
        float da, db, dc, dd;
        upk2(d01, da, db);
        upk2(d23, dc, dd);

        float ta = fabsf(da) + EPSF;
        float tb = fabsf(db) + EPSF;
        float tc = fabsf(dc) + EPSF;
        float td = fabsf(dd) + EPSF;

        float sa_, sb_, sc_, sd_;
        asm("rcp.approx.f32 %0, %1;" : "=f"(sa_) : "f"(ta));
        asm("rcp.approx.f32 %0, %1;" : "=f"(sb_) : "f"(tb));
        asm("rcp.approx.f32 %0, %1;" : "=f"(sc_) : "f"(tc));
        asm("rcp.approx.f32 %0, %1;" : "=f"(sd_) : "f"(td));

        ull s01 = pk2(sa_, sb_);
        ull s23 = pk2(sc_, sd_);
        ull a01 = fma2(s01, L2E2, negm2);
        ull a23 = fma2(s23, L2E2, negm2);
        float aa, ab, ac, ad;
        upk2(a01, aa, ab);
        upk2(a23, ac, ad);

        float ea, eb, ec, ed;
        asm("ex2.approx.f32 %0, %1;" : "=f"(ea) : "f"(aa));
        asm("ex2.approx.f32 %0, %1;" : "=f"(eb) : "f"(ab));
        asm("ex2.approx.f32 %0, %1;" : "=f"(ec) : "f"(ac));
        asm("ex2.approx.f32 %0, %1;" : "=f"(ed) : "f"(ad));

        ull e01 = pk2(ea, eb);
        ull e23 = pk2(ec, ed);
        w2   = add2(w2, e01);
        w2b  = add2(w2b, e23);
        wx2  = fma2(e01, x01, wx2);
        wx2b = fma2(e23, x23, wx2b);
    }
    float wl, wh, wbl, wbh, wxl, wxh, wxbl, wxbh;
    upk2(w2, wl, wh);
    upk2(w2b, wbl, wbh);
    upk2(wx2, wxl, wxh);
    upk2(wx2b, wxbl, wxbh);
    float wsum = (wl + wh) + (wbl + wbh);
    float wx   = (wxl + wxh) + (wxbl + wxbh);

    float rw;
    asm("rcp.approx.f32 %0, %1;" : "=f"(rw) : "f"(wsum));
    // contribution of head h to output i: (av * wx/wsum) / sqrt(d)
    partial[tid] = av * inv_sqrt_d * (wx * rw);
    __syncthreads();

    // ---- Cross-head sum (8 values per output), single coalesced store ----
    if (tid < ITILE) {
        float bconst = 0.0f;
        #pragma unroll
        for (int hh = 0; hh < HH; hh++) bconst += betas[hh * 3 + 2];

        float s = 0.0f;
        #pragma unroll
        for (int hh = 0; hh < HH; hh++) s += partial[hh * ITILE + tid];

        out[b * DD + tile * ITILE + tid] =
            xs[tile * ITILE + tid] + s + bconst * inv_sqrt_d;
    }
}

extern "C" void kernel_launch(void* const* d_in, const int* in_sizes, int n_in,
                              void* d_out, int out_size)
{
    const float* x      = (const float*)d_in[0];
    const float* alphas = (const float*)d_in[1];
    const float* betas  = (const float*)d_in[2];
    float* out = (float*)d_out;

    dim3 grid(NTILES, BB);   // (32, 64) = 2048 CTAs
    dim3 block(NTHR);
    flattn_kernel<<<grid, block>>>(x, alphas, betas, out);
}